// round 7
// baseline (speedup 1.0000x reference)
#include <cuda_runtime.h>
#include <cstdint>
#include <math.h>

// Problem constants
#define TPRIME 510
#define BATCH  32
#define CIN    128
#define TLEN   1024
#define FDIM   256
#define KCONV  640            // CIN * KW
#define HDIM   512
#define GDIM   2048           // 4*H
#define M_ROWS (TPRIME*BATCH) // 16320
#define NCTA_R 128            // persistent CTAs for recurrence
#define WSTR   516            // padded smem row stride (floats) for GEMM kernels

// recurrence smem layout
#define HSW    68             // h slice row stride (floats): 64 + 4 pad, 16B aligned
#define HSWARP (32*HSW)       // 2176 floats per warp slice region
#define PSTR   20             // part: b stride
#define SKS    648            // part: ks stride (32*20 + 8 -> bank shift 8/ks)

// ---------------- packed f32x2 helpers (Blackwell FFMA2 path) ----------------
__device__ __forceinline__ void ffma2(unsigned long long &d,
                                      unsigned long long a,
                                      unsigned long long b) {
    asm("fma.rn.f32x2 %0, %1, %2, %0;" : "+l"(d) : "l"(a), "l"(b));
}
__device__ __forceinline__ unsigned long long pk2(float x) {
    unsigned long long r;
    asm("mov.b64 %0, {%1, %1};" : "=l"(r) : "f"(x));
    return r;
}
__device__ __forceinline__ float2 upk(unsigned long long v) {
    float2 r;
    asm("mov.b64 {%0, %1}, %2;" : "=f"(r.x), "=f"(r.y) : "l"(v));
    return r;
}

// ---------------- scratch -----------------------------------------------------
__device__ float g_Wr[FDIM*KCONV];                    // conv_w transposed [f][k][c]
__device__ float g_feats[(size_t)M_ROWS*FDIM];        // conv output [m][F]
__device__ float g_xp[(size_t)M_ROWS*GDIM];           // x_proj [t*32+b][4H]
__device__ float g_h[2][BATCH*HDIM];                  // double-buffered hidden state
__device__ float g_pu[2][BATCH*NCTA_R];               // partial u-dot [b][cta]
__device__ __align__(16) unsigned g_flagsP[NCTA_R];   // packed per-CTA step flags (512 B)

// ---------------- prep --------------------------------------------------------
__global__ void prep_kernel(const float* __restrict__ conv_w)
{
    int stride = gridDim.x * blockDim.x;
    int i0 = blockIdx.x * blockDim.x + threadIdx.x;
    for (int i = i0; i < FDIM*KCONV; i += stride) {
        int f = i / KCONV;
        int rem = i - f*KCONV;
        int k = rem >> 7;
        int c = rem & 127;
        g_Wr[i] = conv_w[f*KCONV + c*5 + k];
    }
    for (int i = i0; i < BATCH*HDIM; i += stride) g_h[0][i] = 0.f;
    if (i0 < NCTA_R) g_flagsP[i0] = 0u;
}

// ---------------- conv as GEMM: [16320 x 640] * [640 x 256]^T -----------------
__global__ __launch_bounds__(256)
void conv_gemm(const float* __restrict__ x,
               const float* __restrict__ cb,
               const float* __restrict__ gam,
               const float* __restrict__ bet,
               const float* __restrict__ mu,
               const float* __restrict__ var)
{
    __shared__ float As[16][132];
    __shared__ float Bs[16][132];
    const int tid  = threadIdx.x;
    const int mblk = blockIdx.y * 128;
    const int nblk = blockIdx.x * 128;
    const int lrow = tid >> 1;
    const int lk   = (tid & 1) * 8;

    const int m = mblk + lrow;
    const bool mvalid = (m < M_ROWS);
    const float* arow = x;
    if (mvalid) {
        int t = m >> 5, b = m & 31;
        arow = x + (size_t)b * (TLEN*CIN) + (size_t)t * (2*CIN);
    }
    const float* brow = g_Wr + (size_t)(nblk + lrow) * KCONV;

    unsigned long long acc2[8][4];
#pragma unroll
    for (int i = 0; i < 8; i++)
#pragma unroll
        for (int j = 0; j < 4; j++) acc2[i][j] = 0ull;

    const int ty = tid >> 4, tx = tid & 15;

    for (int k0 = 0; k0 < KCONV; k0 += 16) {
        float4 a0 = make_float4(0.f,0.f,0.f,0.f), a1 = a0;
        if (mvalid) {
            a0 = *(const float4*)(arow + k0 + lk);
            a1 = *(const float4*)(arow + k0 + lk + 4);
        }
        float4 b0 = *(const float4*)(brow + k0 + lk);
        float4 b1 = *(const float4*)(brow + k0 + lk + 4);
        __syncthreads();
        As[lk+0][lrow]=a0.x; As[lk+1][lrow]=a0.y; As[lk+2][lrow]=a0.z; As[lk+3][lrow]=a0.w;
        As[lk+4][lrow]=a1.x; As[lk+5][lrow]=a1.y; As[lk+6][lrow]=a1.z; As[lk+7][lrow]=a1.w;
        Bs[lk+0][lrow]=b0.x; Bs[lk+1][lrow]=b0.y; Bs[lk+2][lrow]=b0.z; Bs[lk+3][lrow]=b0.w;
        Bs[lk+4][lrow]=b1.x; Bs[lk+5][lrow]=b1.y; Bs[lk+6][lrow]=b1.z; Bs[lk+7][lrow]=b1.w;
        __syncthreads();
#pragma unroll
        for (int k = 0; k < 16; k++) {
            float a[8];
            *(float4*)&a[0] = *(const float4*)&As[k][ty*4];
            *(float4*)&a[4] = *(const float4*)&As[k][ty*4+64];
            ulonglong2 bq0 = *(const ulonglong2*)&Bs[k][tx*4];
            ulonglong2 bq1 = *(const ulonglong2*)&Bs[k][tx*4+64];
#pragma unroll
            for (int i = 0; i < 8; i++) {
                unsigned long long aa = pk2(a[i]);
                ffma2(acc2[i][0], aa, bq0.x);
                ffma2(acc2[i][1], aa, bq0.y);
                ffma2(acc2[i][2], aa, bq1.x);
                ffma2(acc2[i][3], aa, bq1.y);
            }
        }
    }
#pragma unroll
    for (int j2 = 0; j2 < 4; j2++) {
        int nrel = (j2 < 2) ? (tx*4 + j2*2) : (64 + tx*4 + (j2-2)*2);
#pragma unroll
        for (int h = 0; h < 2; h++) {
            int n = nblk + nrel + h;
            float invv = gam[n] * rsqrtf(var[n] + 1e-5f);
            float addv = bet[n] - mu[n]*invv;
            float cbv  = cb[n];
#pragma unroll
            for (int i = 0; i < 8; i++) {
                int mm = mblk + ((i < 4) ? (ty*4 + i) : (64 + ty*4 + i - 4));
                if (mm < M_ROWS) {
                    float2 p = upk(acc2[i][j2]);
                    float v = ((h == 0) ? p.x : p.y) + cbv;
                    v = fmaxf(v, 0.f);
                    g_feats[(size_t)mm*FDIM + n] = v*invv + addv;
                }
            }
        }
    }
}

// ---------------- x_proj GEMM: [16320 x 256] * [256 x 2048]^T -----------------
__global__ __launch_bounds__(256)
void xproj_gemm(const float* __restrict__ w_ih,
                const float* __restrict__ b_ih,
                const float* __restrict__ b_hh)
{
    __shared__ float As[16][132];
    __shared__ float Bs[16][132];
    const int tid  = threadIdx.x;
    const int mblk = blockIdx.y * 128;
    const int nblk = blockIdx.x * 128;
    const int lrow = tid >> 1;
    const int lk   = (tid & 1) * 8;

    const int m = mblk + lrow;
    const bool mvalid = (m < M_ROWS);
    const float* arow = g_feats + (size_t)(mvalid ? m : 0) * FDIM;
    const float* brow = w_ih + (size_t)(nblk + lrow) * FDIM;

    unsigned long long acc2[8][4];
#pragma unroll
    for (int i = 0; i < 8; i++)
#pragma unroll
        for (int j = 0; j < 4; j++) acc2[i][j] = 0ull;

    const int ty = tid >> 4, tx = tid & 15;

    for (int k0 = 0; k0 < FDIM; k0 += 16) {
        float4 a0 = make_float4(0.f,0.f,0.f,0.f), a1 = a0;
        if (mvalid) {
            a0 = *(const float4*)(arow + k0 + lk);
            a1 = *(const float4*)(arow + k0 + lk + 4);
        }
        float4 b0 = *(const float4*)(brow + k0 + lk);
        float4 b1 = *(const float4*)(brow + k0 + lk + 4);
        __syncthreads();
        As[lk+0][lrow]=a0.x; As[lk+1][lrow]=a0.y; As[lk+2][lrow]=a0.z; As[lk+3][lrow]=a0.w;
        As[lk+4][lrow]=a1.x; As[lk+5][lrow]=a1.y; As[lk+6][lrow]=a1.z; As[lk+7][lrow]=a1.w;
        Bs[lk+0][lrow]=b0.x; Bs[lk+1][lrow]=b0.y; Bs[lk+2][lrow]=b0.z; Bs[lk+3][lrow]=b0.w;
        Bs[lk+4][lrow]=b1.x; Bs[lk+5][lrow]=b1.y; Bs[lk+6][lrow]=b1.z; Bs[lk+7][lrow]=b1.w;
        __syncthreads();
#pragma unroll
        for (int k = 0; k < 16; k++) {
            float a[8];
            *(float4*)&a[0] = *(const float4*)&As[k][ty*4];
            *(float4*)&a[4] = *(const float4*)&As[k][ty*4+64];
            ulonglong2 bq0 = *(const ulonglong2*)&Bs[k][tx*4];
            ulonglong2 bq1 = *(const ulonglong2*)&Bs[k][tx*4+64];
#pragma unroll
            for (int i = 0; i < 8; i++) {
                unsigned long long aa = pk2(a[i]);
                ffma2(acc2[i][0], aa, bq0.x);
                ffma2(acc2[i][1], aa, bq0.y);
                ffma2(acc2[i][2], aa, bq1.x);
                ffma2(acc2[i][3], aa, bq1.y);
            }
        }
    }
#pragma unroll
    for (int j2 = 0; j2 < 4; j2++) {
        int nrel = (j2 < 2) ? (tx*4 + j2*2) : (64 + tx*4 + (j2-2)*2);
#pragma unroll
        for (int h = 0; h < 2; h++) {
            int n = nblk + nrel + h;
            float bias = b_ih[n] + b_hh[n];
#pragma unroll
            for (int i = 0; i < 8; i++) {
                int mm = mblk + ((i < 4) ? (ty*4 + i) : (64 + ty*4 + i - 4));
                if (mm < M_ROWS) {
                    float2 p = upk(acc2[i][j2]);
                    g_xp[(size_t)mm*GDIM + n] = ((h == 0) ? p.x : p.y) + bias;
                }
            }
        }
    }
}

// ---------------- persistent skip-LSTM recurrence -----------------------------
__device__ __forceinline__ float sigf(float v) {
    return __fdividef(1.f, 1.f + __expf(-v));
}
__device__ __forceinline__ float tanh_fast(float v) {
    float x = fminf(fmaxf(v, -15.f), 15.f);
    float e = __expf(2.f * x);
    return __fdividef(e - 1.f, e + 1.f);
}

__global__ __launch_bounds__(256)
void recur_kernel(const float* __restrict__ w_hh,
                  const float* __restrict__ w_uh,
                  const float* __restrict__ b_uh,
                  float* __restrict__ out)
{
    extern __shared__ float sm[];
    float* hs   = sm;                    // [8 warps][32 b][HSW]   (slices of h)
    float* part = hs + 8*HSWARP;         // [16 ks][32 b][PSTR]
    float* us   = part + 16*SKS;         // [32] u state

    const int tid  = threadIdx.x;
    const int warp = tid >> 5;
    const int lane = tid & 31;
    const int cta  = blockIdx.x;
    const int j0   = cta * 4;

    const int r  = tid & 15;             // row 0..15 (q = r>>2, jl = r&3)
    const int ks = tid >> 4;             // k-slice 0..15 (32 k each)

    // ---- w_hh slice into registers: row (q*512 + j0 + jl), k in [ks*32, +32)
    ulonglong2 wreg[8];
    {
        int q = r >> 2, jl = r & 3;
        const float* wsrc = w_hh + (size_t)(q*HDIM + j0 + jl) * HDIM + ks*32;
#pragma unroll
        for (int i = 0; i < 8; i++)
            wreg[i] = *(const ulonglong2*)(wsrc + i*4);
    }
    if (tid < 32) us[tid] = 1.f;
    __syncthreads();

    const float wuh_l = (tid < 128) ? w_uh[j0 + (tid & 3)] : 0.f;
    const float buh   = b_uh[0];

    float c_reg = 0.f;                   // cell state for (b = tid>>2, jl = tid&3), tid<128
    float* hswp = hs + warp*HSWARP;      // this warp's slice region

    for (int t = 0; t < TPRIME; t++) {
        const int ph = t & 1;

        // ---- load this warp's h slice: h[b][64*warp .. +64], 16 float4/lane ----
        const float4* hsrc = reinterpret_cast<const float4*>(g_h[ph]);
        float4 hv[16];
#pragma unroll
        for (int i = 0; i < 16; i++) {
            int f = i*32 + lane;                     // float4 index in slice
            int b = f >> 4, k4 = f & 15;
            hv[i] = __ldcg(hsrc + b*128 + warp*16 + k4);
        }

        // ---- xp gate values for cell update (tid<128: b=tid>>2, jl=tid&3) ----
        float xg[4];
        if (tid < 128) {
            int b = tid >> 2, jl = tid & 3;
            const float* xb = g_xp + ((size_t)t*BATCH + b)*GDIM + j0 + jl;
#pragma unroll
            for (int q = 0; q < 4; q++) xg[q] = __ldcg(xb + q*HDIM);
        }

        // ---- u update from previous step's partials (tid<128, 4 warps) -------
        if (t > 0 && tid < 128) {
            const float4* pp = (const float4*)&g_pu[(t-1)&1][(tid>>2)*NCTA_R + (tid&3)*32];
            float s = 0.f;
#pragma unroll
            for (int i = 0; i < 8; i++) {
                float4 v = __ldcg(pp + i);
                s += v.x + v.y + v.z + v.w;
            }
            s += __shfl_down_sync(0xffffffffu, s, 1);
            s += __shfl_down_sync(0xffffffffu, s, 2);
            if ((tid & 3) == 0) {
                int b = tid >> 2;
                float du = sigf(s + buh);
                float u  = us[b];
                float ub = rintf(u);
                us[b] = ub*du + (1.f-ub)*(u + fminf(du, 1.f-u));
            }
        }

        // ---- stage slice into smem (per-warp; only syncwarp needed) ----------
#pragma unroll
        for (int i = 0; i < 16; i++) {
            int f = i*32 + lane;
            int b = f >> 4, k4 = f & 15;
            *(float4*)&hswp[b*HSW + k4*4] = hv[i];
        }
        __syncwarp();

        // ---- GEMM: acc[b] = dot(w[r][ks*32..+32], h[b][ks*32..+32]) ----------
        const float* hbase = hswp + (ks & 1)*32;
#pragma unroll 4
        for (int b4 = 0; b4 < 32; b4 += 4) {
            unsigned long long a0[4], a1[4];
#pragma unroll
            for (int bb = 0; bb < 4; bb++) { a0[bb] = 0ull; a1[bb] = 0ull; }
#pragma unroll
            for (int i = 0; i < 8; i++) {
#pragma unroll
                for (int bb = 0; bb < 4; bb++) {
                    ulonglong2 hq = *(const ulonglong2*)&hbase[(b4+bb)*HSW + i*4];
                    ffma2(a0[bb], wreg[i].x, hq.x);
                    ffma2(a1[bb], wreg[i].y, hq.y);
                }
            }
#pragma unroll
            for (int bb = 0; bb < 4; bb++) {
                float2 p0 = upk(a0[bb]), p1 = upk(a1[bb]);
                part[ks*SKS + (b4+bb)*PSTR + r] = (p0.x + p0.y) + (p1.x + p1.y);
            }
        }
        __syncthreads();

        // ---- fused k-reduce + cell update (tid<128: b=tid>>2, jl=tid&3) ------
        if (tid < 128) {
            int b  = tid >> 2;
            int jl = tid & 3;
            float g4[4];
#pragma unroll
            for (int q = 0; q < 4; q++) {
                float s = xg[q];
                const float* pp = part + b*PSTR + q*4 + jl;
#pragma unroll
                for (int k2 = 0; k2 < 16; k2++) s += pp[k2*SKS];
                g4[q] = s;
            }
            float u  = us[b];
            float ub = rintf(u);
            float ct = sigf(g4[1])*c_reg + sigf(g4[0])*tanh_fast(g4[2]);
            float ht = sigf(g4[3])*tanh_fast(ct);
            int hw = (j0 + jl) >> 6, ho = (j0 + jl) & 63;
            float hprev = hs[hw*HSWARP + b*HSW + ho];
            float cn = ub*ct + (1.f-ub)*c_reg;
            float hn = ub*ht + (1.f-ub)*hprev;
            c_reg = cn;

            __stcg(&g_h[ph^1][b*HDIM + j0 + jl], hn);
            if (t == TPRIME-1) out[b*HDIM + j0 + jl] = hn;

            float pv = cn * wuh_l;
            pv += __shfl_down_sync(0xffffffffu, pv, 1);
            pv += __shfl_down_sync(0xffffffffu, pv, 2);
            if (jl == 0) __stcg(&g_pu[ph][b*NCTA_R + cta], pv);
        }
        __syncthreads();

        // ---- low-traffic grid barrier (packed flags, 1-warp vector poll) -----
        if (t < TPRIME-1) {
            if (tid == 0) {
                asm volatile("st.release.gpu.global.u32 [%0], %1;"
                             :: "l"(&g_flagsP[cta]), "r"((unsigned)(t+1)) : "memory");
            }
            if (tid < 32) {
                const unsigned tgt = (unsigned)(t+1);
                bool ok;
                do {
                    uint4 v;
                    asm volatile("ld.relaxed.gpu.global.v4.u32 {%0,%1,%2,%3}, [%4];"
                                 : "=r"(v.x), "=r"(v.y), "=r"(v.z), "=r"(v.w)
                                 : "l"(&g_flagsP[lane*4]) : "memory");
                    unsigned mn = min(min(v.x, v.y), min(v.z, v.w));
                    ok = (mn >= tgt);
                } while (!__all_sync(0xffffffffu, ok));
                asm volatile("fence.acq_rel.gpu;" ::: "memory");
            }
            __syncthreads();
        }
    }
}

// ---------------- launch -----------------------------------------------------
extern "C" void kernel_launch(void* const* d_in, const int* in_sizes, int n_in,
                              void* d_out, int out_size)
{
    const float* x      = (const float*)d_in[0];
    const float* conv_w = (const float*)d_in[1];
    const float* conv_b = (const float*)d_in[2];
    const float* gam    = (const float*)d_in[3];
    const float* bet    = (const float*)d_in[4];
    const float* mu     = (const float*)d_in[5];
    const float* var    = (const float*)d_in[6];
    const float* w_ih   = (const float*)d_in[7];
    const float* w_hh   = (const float*)d_in[8];
    const float* b_ih   = (const float*)d_in[9];
    const float* b_hh   = (const float*)d_in[10];
    const float* w_uh   = (const float*)d_in[11];
    const float* b_uh   = (const float*)d_in[12];

    const int smem_recur = (8*HSWARP + 16*SKS + 32) * (int)sizeof(float);
    cudaFuncSetAttribute(recur_kernel, cudaFuncAttributeMaxDynamicSharedMemorySize, smem_recur);

    prep_kernel<<<64, 256>>>(conv_w);
    conv_gemm<<<dim3(2, 128), 256>>>(x, conv_b, gam, bet, mu, var);
    xproj_gemm<<<dim3(16, 128), 256>>>(w_ih, b_ih, b_hh);
    recur_kernel<<<NCTA_R, 256, smem_recur>>>(w_hh, w_uh, b_uh, (float*)d_out);
}

// round 8
// speedup vs baseline: 1.7108x; 1.7108x over previous
#include <cuda_runtime.h>
#include <cstdint>
#include <math.h>

// Problem constants
#define TPRIME 510
#define BATCH  32
#define CIN    128
#define TLEN   1024
#define FDIM   256
#define KCONV  640            // CIN * KW
#define HDIM   512
#define GDIM   2048           // 4*H
#define M_ROWS (TPRIME*BATCH) // 16320
#define NCTA_R 128            // persistent CTAs for recurrence
#define WSTR   516            // padded smem row stride (floats) for GEMM kernels

// recurrence smem layout
// h slice row: 64 floats stored as [0..31][4-float shim][32..63] -> halves at +0 / +36
// (36 mod 32 = 4 banks apart => the two ks lane-groups never collide)
#define HSW    72             // h slice row stride (floats)
#define HSWARP (32*HSW)       // per-warp slice region
#define PSTR   20             // part: b stride
#define SKS    648            // part: ks stride (32*20 + 8 -> bank shift 8/ks)

// ---------------- packed f32x2 helpers (Blackwell FFMA2 path) ----------------
__device__ __forceinline__ void ffma2(unsigned long long &d,
                                      unsigned long long a,
                                      unsigned long long b) {
    asm("fma.rn.f32x2 %0, %1, %2, %0;" : "+l"(d) : "l"(a), "l"(b));
}
__device__ __forceinline__ unsigned long long pk2(float x) {
    unsigned long long r;
    asm("mov.b64 %0, {%1, %1};" : "=l"(r) : "f"(x));
    return r;
}
__device__ __forceinline__ float2 upk(unsigned long long v) {
    float2 r;
    asm("mov.b64 {%0, %1}, %2;" : "=f"(r.x), "=f"(r.y) : "l"(v));
    return r;
}

// ---------------- scratch -----------------------------------------------------
__device__ float g_Wr[FDIM*KCONV];                    // conv_w transposed [f][k][c]
__device__ float g_feats[(size_t)M_ROWS*FDIM];        // conv output [m][F]
__device__ float g_xp[(size_t)M_ROWS*GDIM];           // x_proj [t*32+b][4H]
__device__ float g_h[2][BATCH*HDIM];                  // double-buffered hidden state
__device__ float g_pu[2][BATCH*NCTA_R];               // partial u-dot [b][cta]
__device__ unsigned g_flags[NCTA_R*32];               // per-CTA step flags, 128B apart

// ---------------- prep --------------------------------------------------------
__global__ void prep_kernel(const float* __restrict__ conv_w)
{
    int stride = gridDim.x * blockDim.x;
    int i0 = blockIdx.x * blockDim.x + threadIdx.x;
    for (int i = i0; i < FDIM*KCONV; i += stride) {
        int f = i / KCONV;
        int rem = i - f*KCONV;
        int k = rem >> 7;
        int c = rem & 127;
        g_Wr[i] = conv_w[f*KCONV + c*5 + k];
    }
    for (int i = i0; i < BATCH*HDIM; i += stride) g_h[0][i] = 0.f;
    for (int i = i0; i < NCTA_R*32; i += stride) g_flags[i] = 0u;
}

// ---------------- conv as GEMM: [16320 x 640] * [640 x 256]^T -----------------
__global__ __launch_bounds__(256)
void conv_gemm(const float* __restrict__ x,
               const float* __restrict__ cb,
               const float* __restrict__ gam,
               const float* __restrict__ bet,
               const float* __restrict__ mu,
               const float* __restrict__ var)
{
    __shared__ float As[16][132];
    __shared__ float Bs[16][132];
    const int tid  = threadIdx.x;
    const int mblk = blockIdx.y * 128;
    const int nblk = blockIdx.x * 128;
    const int lrow = tid >> 1;
    const int lk   = (tid & 1) * 8;

    const int m = mblk + lrow;
    const bool mvalid = (m < M_ROWS);
    const float* arow = x;
    if (mvalid) {
        int t = m >> 5, b = m & 31;
        arow = x + (size_t)b * (TLEN*CIN) + (size_t)t * (2*CIN);
    }
    const float* brow = g_Wr + (size_t)(nblk + lrow) * KCONV;

    unsigned long long acc2[8][4];
#pragma unroll
    for (int i = 0; i < 8; i++)
#pragma unroll
        for (int j = 0; j < 4; j++) acc2[i][j] = 0ull;

    const int ty = tid >> 4, tx = tid & 15;

    for (int k0 = 0; k0 < KCONV; k0 += 16) {
        float4 a0 = make_float4(0.f,0.f,0.f,0.f), a1 = a0;
        if (mvalid) {
            a0 = *(const float4*)(arow + k0 + lk);
            a1 = *(const float4*)(arow + k0 + lk + 4);
        }
        float4 b0 = *(const float4*)(brow + k0 + lk);
        float4 b1 = *(const float4*)(brow + k0 + lk + 4);
        __syncthreads();
        As[lk+0][lrow]=a0.x; As[lk+1][lrow]=a0.y; As[lk+2][lrow]=a0.z; As[lk+3][lrow]=a0.w;
        As[lk+4][lrow]=a1.x; As[lk+5][lrow]=a1.y; As[lk+6][lrow]=a1.z; As[lk+7][lrow]=a1.w;
        Bs[lk+0][lrow]=b0.x; Bs[lk+1][lrow]=b0.y; Bs[lk+2][lrow]=b0.z; Bs[lk+3][lrow]=b0.w;
        Bs[lk+4][lrow]=b1.x; Bs[lk+5][lrow]=b1.y; Bs[lk+6][lrow]=b1.z; Bs[lk+7][lrow]=b1.w;
        __syncthreads();
#pragma unroll
        for (int k = 0; k < 16; k++) {
            float a[8];
            *(float4*)&a[0] = *(const float4*)&As[k][ty*4];
            *(float4*)&a[4] = *(const float4*)&As[k][ty*4+64];
            ulonglong2 bq0 = *(const ulonglong2*)&Bs[k][tx*4];
            ulonglong2 bq1 = *(const ulonglong2*)&Bs[k][tx*4+64];
#pragma unroll
            for (int i = 0; i < 8; i++) {
                unsigned long long aa = pk2(a[i]);
                ffma2(acc2[i][0], aa, bq0.x);
                ffma2(acc2[i][1], aa, bq0.y);
                ffma2(acc2[i][2], aa, bq1.x);
                ffma2(acc2[i][3], aa, bq1.y);
            }
        }
    }
#pragma unroll
    for (int j2 = 0; j2 < 4; j2++) {
        int nrel = (j2 < 2) ? (tx*4 + j2*2) : (64 + tx*4 + (j2-2)*2);
#pragma unroll
        for (int h = 0; h < 2; h++) {
            int n = nblk + nrel + h;
            float invv = gam[n] * rsqrtf(var[n] + 1e-5f);
            float addv = bet[n] - mu[n]*invv;
            float cbv  = cb[n];
#pragma unroll
            for (int i = 0; i < 8; i++) {
                int mm = mblk + ((i < 4) ? (ty*4 + i) : (64 + ty*4 + i - 4));
                if (mm < M_ROWS) {
                    float2 p = upk(acc2[i][j2]);
                    float v = ((h == 0) ? p.x : p.y) + cbv;
                    v = fmaxf(v, 0.f);
                    g_feats[(size_t)mm*FDIM + n] = v*invv + addv;
                }
            }
        }
    }
}

// ---------------- x_proj GEMM: [16320 x 256] * [256 x 2048]^T -----------------
__global__ __launch_bounds__(256)
void xproj_gemm(const float* __restrict__ w_ih,
                const float* __restrict__ b_ih,
                const float* __restrict__ b_hh)
{
    __shared__ float As[16][132];
    __shared__ float Bs[16][132];
    const int tid  = threadIdx.x;
    const int mblk = blockIdx.y * 128;
    const int nblk = blockIdx.x * 128;
    const int lrow = tid >> 1;
    const int lk   = (tid & 1) * 8;

    const int m = mblk + lrow;
    const bool mvalid = (m < M_ROWS);
    const float* arow = g_feats + (size_t)(mvalid ? m : 0) * FDIM;
    const float* brow = w_ih + (size_t)(nblk + lrow) * FDIM;

    unsigned long long acc2[8][4];
#pragma unroll
    for (int i = 0; i < 8; i++)
#pragma unroll
        for (int j = 0; j < 4; j++) acc2[i][j] = 0ull;

    const int ty = tid >> 4, tx = tid & 15;

    for (int k0 = 0; k0 < FDIM; k0 += 16) {
        float4 a0 = make_float4(0.f,0.f,0.f,0.f), a1 = a0;
        if (mvalid) {
            a0 = *(const float4*)(arow + k0 + lk);
            a1 = *(const float4*)(arow + k0 + lk + 4);
        }
        float4 b0 = *(const float4*)(brow + k0 + lk);
        float4 b1 = *(const float4*)(brow + k0 + lk + 4);
        __syncthreads();
        As[lk+0][lrow]=a0.x; As[lk+1][lrow]=a0.y; As[lk+2][lrow]=a0.z; As[lk+3][lrow]=a0.w;
        As[lk+4][lrow]=a1.x; As[lk+5][lrow]=a1.y; As[lk+6][lrow]=a1.z; As[lk+7][lrow]=a1.w;
        Bs[lk+0][lrow]=b0.x; Bs[lk+1][lrow]=b0.y; Bs[lk+2][lrow]=b0.z; Bs[lk+3][lrow]=b0.w;
        Bs[lk+4][lrow]=b1.x; Bs[lk+5][lrow]=b1.y; Bs[lk+6][lrow]=b1.z; Bs[lk+7][lrow]=b1.w;
        __syncthreads();
#pragma unroll
        for (int k = 0; k < 16; k++) {
            float a[8];
            *(float4*)&a[0] = *(const float4*)&As[k][ty*4];
            *(float4*)&a[4] = *(const float4*)&As[k][ty*4+64];
            ulonglong2 bq0 = *(const ulonglong2*)&Bs[k][tx*4];
            ulonglong2 bq1 = *(const ulonglong2*)&Bs[k][tx*4+64];
#pragma unroll
            for (int i = 0; i < 8; i++) {
                unsigned long long aa = pk2(a[i]);
                ffma2(acc2[i][0], aa, bq0.x);
                ffma2(acc2[i][1], aa, bq0.y);
                ffma2(acc2[i][2], aa, bq1.x);
                ffma2(acc2[i][3], aa, bq1.y);
            }
        }
    }
#pragma unroll
    for (int j2 = 0; j2 < 4; j2++) {
        int nrel = (j2 < 2) ? (tx*4 + j2*2) : (64 + tx*4 + (j2-2)*2);
#pragma unroll
        for (int h = 0; h < 2; h++) {
            int n = nblk + nrel + h;
            float bias = b_ih[n] + b_hh[n];
#pragma unroll
            for (int i = 0; i < 8; i++) {
                int mm = mblk + ((i < 4) ? (ty*4 + i) : (64 + ty*4 + i - 4));
                if (mm < M_ROWS) {
                    float2 p = upk(acc2[i][j2]);
                    g_xp[(size_t)mm*GDIM + n] = ((h == 0) ? p.x : p.y) + bias;
                }
            }
        }
    }
}

// ---------------- persistent skip-LSTM recurrence -----------------------------
__device__ __forceinline__ float sigf(float v) {
    return __fdividef(1.f, 1.f + __expf(-v));
}
__device__ __forceinline__ float tanh_fast(float v) {
    float x = fminf(fmaxf(v, -15.f), 15.f);
    float e = __expf(2.f * x);
    return __fdividef(e - 1.f, e + 1.f);
}

__global__ __launch_bounds__(256)
void recur_kernel(const float* __restrict__ w_hh,
                  const float* __restrict__ w_uh,
                  const float* __restrict__ b_uh,
                  float* __restrict__ out)
{
    extern __shared__ float sm[];
    float* hs   = sm;                    // [8 warps][32 b][HSW]   (slices of h, shimmed rows)
    float* part = hs + 8*HSWARP;         // [16 ks][32 b][PSTR]
    float* us   = part + 16*SKS;         // [32] u state

    const int tid  = threadIdx.x;
    const int warp = tid >> 5;
    const int lane = tid & 31;
    const int cta  = blockIdx.x;
    const int j0   = cta * 4;

    const int r  = tid & 15;             // row 0..15 (q = r>>2, jl = r&3)
    const int ks = tid >> 4;             // k-slice 0..15 (32 k each)

    // ---- w_hh slice into registers: row (q*512 + j0 + jl), k in [ks*32, +32)
    ulonglong2 wreg[8];
    {
        int q = r >> 2, jl = r & 3;
        const float* wsrc = w_hh + (size_t)(q*HDIM + j0 + jl) * HDIM + ks*32;
#pragma unroll
        for (int i = 0; i < 8; i++)
            wreg[i] = *(const ulonglong2*)(wsrc + i*4);
    }
    if (tid < 32) us[tid] = 1.f;
    __syncthreads();

    const float wuh_l = (tid < 128) ? w_uh[j0 + (tid & 3)] : 0.f;
    const float buh   = b_uh[0];

    float c_reg = 0.f;                   // cell state for (b = tid>>2, jl = tid&3), tid<128
    float* hswp = hs + warp*HSWARP;      // this warp's slice region

    for (int t = 0; t < TPRIME; t++) {
        const int ph = t & 1;

        // ---- load this warp's h slice: h[b][64*warp .. +64], 16 float4/lane ----
        const float4* hsrc = reinterpret_cast<const float4*>(g_h[ph]);
        float4 hv[16];
#pragma unroll
        for (int i = 0; i < 16; i++) {
            int f = i*32 + lane;                     // float4 index in slice
            int b = f >> 4, k4 = f & 15;
            hv[i] = __ldcg(hsrc + b*128 + warp*16 + k4);
        }

        // ---- xp gate values for cell update (tid<128: b=tid>>2, jl=tid&3) ----
        float xg[4];
        if (tid < 128) {
            int b = tid >> 2, jl = tid & 3;
            const float* xb = g_xp + ((size_t)t*BATCH + b)*GDIM + j0 + jl;
#pragma unroll
            for (int q = 0; q < 4; q++) xg[q] = __ldcg(xb + q*HDIM);
        }

        // ---- u update from previous step's partials (tid<128, 4 warps) -------
        if (t > 0 && tid < 128) {
            const float4* pp = (const float4*)&g_pu[(t-1)&1][(tid>>2)*NCTA_R + (tid&3)*32];
            float s = 0.f;
#pragma unroll
            for (int i = 0; i < 8; i++) {
                float4 v = __ldcg(pp + i);
                s += v.x + v.y + v.z + v.w;
            }
            s += __shfl_down_sync(0xffffffffu, s, 1);
            s += __shfl_down_sync(0xffffffffu, s, 2);
            if ((tid & 3) == 0) {
                int b = tid >> 2;
                float du = sigf(s + buh);
                float u  = us[b];
                float ub = rintf(u);
                us[b] = ub*du + (1.f-ub)*(u + fminf(du, 1.f-u));
            }
        }

        // ---- stage slice into smem (per-warp; shimmed row layout) ------------
#pragma unroll
        for (int i = 0; i < 16; i++) {
            int f = i*32 + lane;
            int b = f >> 4, k4 = f & 15;
            int off = k4*4 + ((k4 >> 3) << 2);       // halves at +0 / +36 floats
            *(float4*)&hswp[b*HSW + off] = hv[i];
        }
        __syncwarp();

        // ---- GEMM: acc[b] = dot(w[r][ks*32..+32], h[b][ks*32..+32]) ----------
        // lane groups (ks even/odd) read +0 / +36 floats -> different banks,
        // broadcast within each 16-lane group -> conflict-free LDS.128
        const float* hbase = hswp + (ks & 1)*36;
#pragma unroll 4
        for (int b4 = 0; b4 < 32; b4 += 4) {
            unsigned long long a0[4], a1[4];
#pragma unroll
            for (int bb = 0; bb < 4; bb++) { a0[bb] = 0ull; a1[bb] = 0ull; }
#pragma unroll
            for (int i = 0; i < 8; i++) {
#pragma unroll
                for (int bb = 0; bb < 4; bb++) {
                    ulonglong2 hq = *(const ulonglong2*)&hbase[(b4+bb)*HSW + i*4];
                    ffma2(a0[bb], wreg[i].x, hq.x);
                    ffma2(a1[bb], wreg[i].y, hq.y);
                }
            }
#pragma unroll
            for (int bb = 0; bb < 4; bb++) {
                float2 p0 = upk(a0[bb]), p1 = upk(a1[bb]);
                part[ks*SKS + (b4+bb)*PSTR + r] = (p0.x + p0.y) + (p1.x + p1.y);
            }
        }
        __syncthreads();

        // ---- fused k-reduce + cell update (tid<128: b=tid>>2, jl=tid&3) ------
        if (tid < 128) {
            int b  = tid >> 2;
            int jl = tid & 3;
            float g4[4];
#pragma unroll
            for (int q = 0; q < 4; q++) {
                float s = xg[q];
                const float* pp = part + b*PSTR + q*4 + jl;
#pragma unroll
                for (int k2 = 0; k2 < 16; k2++) s += pp[k2*SKS];
                g4[q] = s;
            }
            float u  = us[b];
            float ub = rintf(u);
            float ct = sigf(g4[1])*c_reg + sigf(g4[0])*tanh_fast(g4[2]);
            float ht = sigf(g4[3])*tanh_fast(ct);
            int hidx = j0 + jl;
            int hw = hidx >> 6;
            int ho = hidx & 63;
            int hoff = ho + ((ho >> 5) << 2);        // shimmed row offset
            float hprev = hs[hw*HSWARP + b*HSW + hoff];
            float cn = ub*ct + (1.f-ub)*c_reg;
            float hn = ub*ht + (1.f-ub)*hprev;
            c_reg = cn;

            __stcg(&g_h[ph^1][b*HDIM + j0 + jl], hn);
            if (t == TPRIME-1) out[b*HDIM + j0 + jl] = hn;

            float pv = cn * wuh_l;
            pv += __shfl_down_sync(0xffffffffu, pv, 1);
            pv += __shfl_down_sync(0xffffffffu, pv, 2);
            if (jl == 0) __stcg(&g_pu[ph][b*NCTA_R + cta], pv);
        }
        __syncthreads();

        // ---- distributed-flag grid barrier (R5 proven: padded lines) ---------
        if (t < TPRIME-1) {
            if (tid == 0) {
                asm volatile("st.release.gpu.global.u32 [%0], %1;"
                             :: "l"(&g_flags[cta*32]), "r"((unsigned)(t+1)) : "memory");
            }
            if (tid < NCTA_R) {
                unsigned v;
                do {
                    asm volatile("ld.acquire.gpu.global.u32 %0, [%1];"
                                 : "=r"(v) : "l"(&g_flags[tid*32]) : "memory");
                } while (v < (unsigned)(t+1));
            }
            __syncthreads();
        }
    }
}

// ---------------- launch -----------------------------------------------------
extern "C" void kernel_launch(void* const* d_in, const int* in_sizes, int n_in,
                              void* d_out, int out_size)
{
    const float* x      = (const float*)d_in[0];
    const float* conv_w = (const float*)d_in[1];
    const float* conv_b = (const float*)d_in[2];
    const float* gam    = (const float*)d_in[3];
    const float* bet    = (const float*)d_in[4];
    const float* mu     = (const float*)d_in[5];
    const float* var    = (const float*)d_in[6];
    const float* w_ih   = (const float*)d_in[7];
    const float* w_hh   = (const float*)d_in[8];
    const float* b_ih   = (const float*)d_in[9];
    const float* b_hh   = (const float*)d_in[10];
    const float* w_uh   = (const float*)d_in[11];
    const float* b_uh   = (const float*)d_in[12];

    const int smem_recur = (8*HSWARP + 16*SKS + 32) * (int)sizeof(float);
    cudaFuncSetAttribute(recur_kernel, cudaFuncAttributeMaxDynamicSharedMemorySize, smem_recur);

    prep_kernel<<<64, 256>>>(conv_w);
    conv_gemm<<<dim3(2, 128), 256>>>(x, conv_b, gam, bet, mu, var);
    xproj_gemm<<<dim3(16, 128), 256>>>(w_ih, b_ih, b_hh);
    recur_kernel<<<NCTA_R, 256, smem_recur>>>(w_hh, w_uh, b_uh, (float*)d_out);
}